// round 1
// baseline (speedup 1.0000x reference)
#include <cuda_runtime.h>
#include <cuda_bf16.h>

// Problem dims
#define NB 64     // batch
#define CC 64     // channels in/out
#define TT 256    // frames
#define VV 25     // joints
#define KK 3      // subsets
#define DD 192    // K*C_OUT
#define TV 6400   // TT*VV per (n,c)
#define NSF 409600.0f

typedef unsigned long long u64;

// ---------------- scratch (static device globals; no allocation) ----------------
__device__ float g_y[(size_t)NB * DD * TV];     // 314.6 MB intermediate y
__device__ float g_z[(size_t)NB * CC * TV];     // 104.9 MB intermediate z
__device__ float g_stat0[2 * DD];               // sum, sumsq per d
__device__ float g_stat1[2 * CC];               // sum, sumsq per c
__device__ float g_A2[DD * VV * 26];            // BN0-folded normalized adjacency, w padded to 26
__device__ float g_cvec[CC * VV];               // BN0 beta term pushed through adjacency
__device__ float g_ab1[2 * CC];                 // final BN scale/shift

// ---------------- packed f32x2 helpers ----------------
__device__ __forceinline__ u64 pack2(float x, float y) {
    u64 r; asm("mov.b64 %0, {%1, %2};" : "=l"(r) : "f"(x), "f"(y)); return r;
}
__device__ __forceinline__ u64 dup2(float x) {
    u64 r; asm("mov.b64 %0, {%1, %1};" : "=l"(r) : "f"(x)); return r;
}
__device__ __forceinline__ void unpack2(u64 v, float& x, float& y) {
    asm("mov.b64 {%0, %1}, %2;" : "=f"(x), "=f"(y) : "l"(v));
}
__device__ __forceinline__ u64 ffma2(u64 a, u64 b, u64 c) {
    u64 d; asm("fma.rn.f32x2 %0, %1, %2, %3;" : "=l"(d) : "l"(a), "l"(b), "l"(c)); return d;
}

// ---------------- reduction helper (256-thread block, 2 values) ----------------
__device__ __forceinline__ void block_reduce2(float& s, float& ss) {
    __shared__ float red[16];
    #pragma unroll
    for (int off = 16; off; off >>= 1) {
        s  += __shfl_xor_sync(0xffffffffu, s,  off);
        ss += __shfl_xor_sync(0xffffffffu, ss, off);
    }
    int wid = threadIdx.x >> 5;
    if ((threadIdx.x & 31) == 0) { red[wid] = s; red[8 + wid] = ss; }
    __syncthreads();
    if (threadIdx.x < 8) {
        s = red[threadIdx.x]; ss = red[8 + threadIdx.x];
        #pragma unroll
        for (int off = 4; off; off >>= 1) {
            s  += __shfl_xor_sync(0xffu, s,  off);
            ss += __shfl_xor_sync(0xffu, ss, off);
        }
    }
}

// ---------------- k0: zero accumulators ----------------
__global__ void dgcn_k0_init() {
    int tid = threadIdx.x;
    for (int i = tid; i < 2 * DD; i += 512) g_stat0[i] = 0.f;
    for (int i = tid; i < 2 * CC; i += 512) g_stat1[i] = 0.f;
    for (int i = tid; i < CC * VV; i += 512) g_cvec[i] = 0.f;
}

// ---------------- k1: pointwise GEMM  y[n,d,tv] = sum_c x0[n,c,tv] * W[c,d] + bias[d] ----------------
// grid (25, 64): blockIdx.x = tv tile of 256, blockIdx.y = n. 256 threads, 1 tv each.
// Accumulate 32 d's per chunk as 16 packed f32x2 (d-pairs). W pairs via LDS.64 broadcast.
__global__ void __launch_bounds__(256) dgcn_k1_gemm(
    const float* __restrict__ x0, const float* __restrict__ W, const float* __restrict__ bias)
{
    extern __shared__ float sm[];
    float* ws = sm;            // [64][192]
    float* xs = sm + CC * DD;  // [64][256]
    const int tid = threadIdx.x;
    const int n = blockIdx.y;
    const int tv0 = blockIdx.x * 256;

    // cooperative loads (float4, all aligned)
    {
        const float4* W4 = (const float4*)W;
        float4* ws4 = (float4*)ws;
        #pragma unroll 4
        for (int i = tid; i < CC * DD / 4; i += 256) ws4[i] = W4[i];
        float4* xs4 = (float4*)xs;
        #pragma unroll 4
        for (int i = tid; i < CC * 256 / 4; i += 256) {
            int c = i >> 6, j = i & 63;
            xs4[i] = *(const float4*)(x0 + (size_t)(n * CC + c) * TV + tv0 + 4 * j);
        }
    }
    __syncthreads();

    #pragma unroll 1
    for (int dc = 0; dc < 6; ++dc) {
        const int d0 = dc * 32;
        u64 acc[16];
        #pragma unroll
        for (int i = 0; i < 16; ++i)
            acc[i] = pack2(__ldg(bias + d0 + 2 * i), __ldg(bias + d0 + 2 * i + 1));

        #pragma unroll 4
        for (int c = 0; c < CC; ++c) {
            u64 xp = dup2(xs[c * 256 + tid]);
            const u64* wrow = (const u64*)(ws + c * DD + d0);
            #pragma unroll
            for (int i = 0; i < 16; ++i) acc[i] = ffma2(xp, wrow[i], acc[i]);
        }

        float* yb = g_y + (size_t)n * DD * TV + (size_t)d0 * TV + tv0 + tid;
        #pragma unroll
        for (int i = 0; i < 16; ++i) {
            float lo, hi; unpack2(acc[i], lo, hi);
            yb[(size_t)(2 * i) * TV]     = lo;
            yb[(size_t)(2 * i + 1) * TV] = hi;
        }
    }
}

// ---------------- k1b: per-channel-d stats of y ----------------
// grid (192, 64): blockIdx.x = d, blockIdx.y = n
__global__ void __launch_bounds__(256) dgcn_k1b_stats() {
    const int d = blockIdx.x, n = blockIdx.y, tid = threadIdx.x;
    const float* row = g_y + (size_t)(n * DD + d) * TV;
    float s = 0.f, ss = 0.f;
    #pragma unroll 5
    for (int i = tid; i < TV; i += 256) { float v = row[i]; s += v; ss += v * v; }
    block_reduce2(s, ss);
    if (tid == 0) { atomicAdd(&g_stat0[d], s); atomicAdd(&g_stat0[DD + d], ss); }
}

// ---------------- k2: fold BN0 into normalized adjacency ----------------
// grid 192 blocks (one per d = k*64+c), 32 threads (lane = column w)
__global__ void dgcn_k2_fold(const float* __restrict__ dA,
                             const float* __restrict__ g0, const float* __restrict__ b0)
{
    const int d = blockIdx.x;
    const int k = d >> 6, c = d & 63, grp = c & 7;
    const int w = threadIdx.x;
    const float* A = dA + (size_t)(k * 8 + grp) * VV * VV;

    float deg = 0.f;
    if (w < VV) {
        #pragma unroll
        for (int v = 0; v < VV; ++v) deg += A[v * VV + w];
    }
    const float mean = g_stat0[d] * (1.0f / NSF);
    const float var  = g_stat0[DD + d] * (1.0f / NSF) - mean * mean;
    const float a = g0[d] * rsqrtf(var + 1e-5f);
    const float b = b0[d] - a * mean;
    const float inv = a / (deg + 1e-3f);

    float* A2 = g_A2 + (size_t)d * VV * 26;
    for (int v = 0; v < VV; ++v) {
        if (w < 26) A2[v * 26 + w] = (w < VV) ? A[v * VV + w] * inv : 0.f;
    }
    if (w < VV) atomicAdd(&g_cvec[c * VV + w], b * deg / (deg + 1e-3f));
}

// ---------------- k3: graph propagation + z stats ----------------
// z[n,c,t,w] = sum_{k,v} y[n,k*64+c,t,v] * A2[k,c,v,w] + cvec[c,w]
// grid (64, 32): blockIdx.x = c; blockIdx.y*256+tid -> (n, t-pair). Pack t/t+1 in f32x2 lanes.
__global__ void __launch_bounds__(256) dgcn_k3_prop() {
    __shared__ u64 a2s[KK * VV * 26];   // value duplicated into both lanes
    __shared__ float cvs[VV];
    const int tid = threadIdx.x;
    const int c = blockIdx.x;

    for (int i = tid; i < KK * VV * 26; i += 256) {
        int k = i / (VV * 26);
        int rem = i - k * (VV * 26);
        float v = g_A2[(size_t)((k << 6) + c) * VV * 26 + rem];
        a2s[i] = pack2(v, v);
    }
    if (tid < VV) cvs[tid] = g_cvec[c * VV + tid];
    __syncthreads();

    const int p = blockIdx.y * 256 + tid;   // 0..8191
    const int n = p >> 7;
    const int t = (p & 127) << 1;

    u64 acc[VV];
    #pragma unroll
    for (int w = 0; w < VV; ++w) acc[w] = 0ull;

    #pragma unroll
    for (int k = 0; k < KK; ++k) {
        const float* yb = g_y + ((size_t)(n * DD + (k << 6) + c) * TT + t) * VV;
        const u64* arow = a2s + k * VV * 26;
        #pragma unroll 1
        for (int v = 0; v < VV; ++v) {
            u64 yp = pack2(yb[v], yb[VV + v]);
            const u64* ar = arow + v * 26;
            #pragma unroll
            for (int w = 0; w < VV; ++w) acc[w] = ffma2(yp, ar[w], acc[w]);
        }
    }

    float s = 0.f, ss = 0.f;
    float* zb = g_z + ((size_t)(n * CC + c) * TT + t) * VV;
    #pragma unroll
    for (int w = 0; w < VV; ++w) {
        float lo, hi; unpack2(acc[w], lo, hi);
        float cv = cvs[w];
        lo += cv; hi += cv;
        zb[w] = lo; zb[VV + w] = hi;
        s += lo + hi; ss += lo * lo + hi * hi;
    }
    block_reduce2(s, ss);
    if (tid == 0) { atomicAdd(&g_stat1[c], s); atomicAdd(&g_stat1[CC + c], ss); }
}

// ---------------- k4: final BN fold ----------------
__global__ void dgcn_k4_bn(const float* __restrict__ g1, const float* __restrict__ b1) {
    int c = threadIdx.x;
    if (c < CC) {
        float mean = g_stat1[c] * (1.0f / NSF);
        float var  = g_stat1[CC + c] * (1.0f / NSF) - mean * mean;
        float a = g1[c] * rsqrtf(var + 1e-5f);
        g_ab1[c] = a;
        g_ab1[CC + c] = b1[c] - a * mean;
    }
}

// ---------------- k5: out = relu(a_c * z + b_c + x0) ----------------
__global__ void __launch_bounds__(256) dgcn_k5_out(const float* __restrict__ x0, float* __restrict__ out) {
    int i = blockIdx.x * 256 + threadIdx.x;       // float4 index, exact coverage
    int c = (i / 1600) & 63;                      // 1600 float4 per (n,c)
    float a = g_ab1[c], b = g_ab1[CC + c];
    float4 zv = ((const float4*)g_z)[i];
    float4 xv = ((const float4*)x0)[i];
    float4 o;
    o.x = fmaxf(fmaf(a, zv.x, b) + xv.x, 0.f);
    o.y = fmaxf(fmaf(a, zv.y, b) + xv.y, 0.f);
    o.z = fmaxf(fmaf(a, zv.z, b) + xv.z, 0.f);
    o.w = fmaxf(fmaf(a, zv.w, b) + xv.w, 0.f);
    ((float4*)out)[i] = o;
}

// ---------------- launch ----------------
extern "C" void kernel_launch(void* const* d_in, const int* in_sizes, int n_in,
                              void* d_out, int out_size)
{
    const float* x0   = (const float*)d_in[0];
    const float* dA   = (const float*)d_in[1];
    const float* W    = (const float*)d_in[2];
    const float* bias = (const float*)d_in[3];
    const float* g0   = (const float*)d_in[4];
    const float* b0   = (const float*)d_in[5];
    const float* g1   = (const float*)d_in[6];
    const float* b1   = (const float*)d_in[7];
    float* out = (float*)d_out;

    const int smem1 = (CC * DD + CC * 256) * (int)sizeof(float);  // 114688
    cudaFuncSetAttribute(dgcn_k1_gemm, cudaFuncAttributeMaxDynamicSharedMemorySize, smem1);

    dgcn_k0_init<<<1, 512>>>();
    dgcn_k1_gemm<<<dim3(25, NB), 256, smem1>>>(x0, W, bias);
    dgcn_k1b_stats<<<dim3(DD, NB), 256>>>();
    dgcn_k2_fold<<<DD, 32>>>(dA, g0, b0);
    dgcn_k3_prop<<<dim3(CC, 32), 256>>>();
    dgcn_k4_bn<<<1, 64>>>(g1, b1);
    dgcn_k5_out<<<(NB * CC * TV) / (4 * 256), 256>>>(x0, out);
}

// round 2
// speedup vs baseline: 1.0000x; 1.0000x over previous
#include <cuda_runtime.h>
#include <cuda_bf16.h>

// Problem dims
#define NB 64     // batch
#define CC 64     // channels in/out
#define TT 256    // frames
#define VV 25     // joints
#define KK 3      // subsets
#define DD 192    // K*C_OUT
#define TV 6400   // TT*VV per (n,c)
#define NSF 409600.0f

typedef unsigned long long u64;

// ---------------- scratch (static device globals; no allocation) ----------------
__device__ float g_y[(size_t)NB * DD * TV];     // 314.6 MB intermediate y
__device__ float g_z[(size_t)NB * CC * TV];     // 104.9 MB intermediate z
__device__ float g_stat0[2 * DD];               // sum, sumsq per d
__device__ float g_stat1[2 * CC];               // sum, sumsq per c
__device__ float g_A2[DD * VV * 26];            // BN0-folded normalized adjacency, w padded to 26
__device__ float g_cvec[CC * VV];               // BN0 beta term pushed through adjacency
__device__ float g_ab1[2 * CC];                 // final BN scale/shift

// ---------------- packed f32x2 helpers ----------------
__device__ __forceinline__ u64 pack2(float x, float y) {
    u64 r; asm("mov.b64 %0, {%1, %2};" : "=l"(r) : "f"(x), "f"(y)); return r;
}
__device__ __forceinline__ u64 dup2(float x) {
    u64 r; asm("mov.b64 %0, {%1, %1};" : "=l"(r) : "f"(x)); return r;
}
__device__ __forceinline__ void unpack2(u64 v, float& x, float& y) {
    asm("mov.b64 {%0, %1}, %2;" : "=f"(x), "=f"(y) : "l"(v));
}
__device__ __forceinline__ u64 ffma2(u64 a, u64 b, u64 c) {
    u64 d; asm("fma.rn.f32x2 %0, %1, %2, %3;" : "=l"(d) : "l"(a), "l"(b), "l"(c)); return d;
}

// ---------------- reduction helper (256-thread block, 2 values) ----------------
__device__ __forceinline__ void block_reduce2(float& s, float& ss) {
    __shared__ float red[16];
    #pragma unroll
    for (int off = 16; off; off >>= 1) {
        s  += __shfl_xor_sync(0xffffffffu, s,  off);
        ss += __shfl_xor_sync(0xffffffffu, ss, off);
    }
    int wid = threadIdx.x >> 5;
    if ((threadIdx.x & 31) == 0) { red[wid] = s; red[8 + wid] = ss; }
    __syncthreads();
    if (threadIdx.x < 8) {
        s = red[threadIdx.x]; ss = red[8 + threadIdx.x];
        #pragma unroll
        for (int off = 4; off; off >>= 1) {
            s  += __shfl_xor_sync(0xffu, s,  off);
            ss += __shfl_xor_sync(0xffu, ss, off);
        }
    }
}

// ---------------- k0: zero accumulators ----------------
__global__ void dgcn_k0_init() {
    int tid = threadIdx.x;
    for (int i = tid; i < 2 * DD; i += 512) g_stat0[i] = 0.f;
    for (int i = tid; i < 2 * CC; i += 512) g_stat1[i] = 0.f;
    for (int i = tid; i < CC * VV; i += 512) g_cvec[i] = 0.f;
}

// ---------------- k1: pointwise GEMM  y[n,d,tv] = sum_c x0[n,c,tv] * W[c,d] + bias[d] ----------------
// grid (25, 64): blockIdx.x = tv tile of 256, blockIdx.y = n. 256 threads, 1 tv each.
// Accumulate 32 d's per chunk as 16 packed f32x2 (d-pairs). W pairs via LDS.64 broadcast.
__global__ void __launch_bounds__(256) dgcn_k1_gemm(
    const float* __restrict__ x0, const float* __restrict__ W, const float* __restrict__ bias)
{
    extern __shared__ float sm[];
    float* ws = sm;            // [64][192]
    float* xs = sm + CC * DD;  // [64][256]
    const int tid = threadIdx.x;
    const int n = blockIdx.y;
    const int tv0 = blockIdx.x * 256;

    // cooperative loads (float4, all aligned)
    {
        const float4* W4 = (const float4*)W;
        float4* ws4 = (float4*)ws;
        #pragma unroll 4
        for (int i = tid; i < CC * DD / 4; i += 256) ws4[i] = W4[i];
        float4* xs4 = (float4*)xs;
        #pragma unroll 4
        for (int i = tid; i < CC * 256 / 4; i += 256) {
            int c = i >> 6, j = i & 63;
            xs4[i] = *(const float4*)(x0 + (size_t)(n * CC + c) * TV + tv0 + 4 * j);
        }
    }
    __syncthreads();

    #pragma unroll 1
    for (int dc = 0; dc < 6; ++dc) {
        const int d0 = dc * 32;
        u64 acc[16];
        #pragma unroll
        for (int i = 0; i < 16; ++i)
            acc[i] = pack2(__ldg(bias + d0 + 2 * i), __ldg(bias + d0 + 2 * i + 1));

        #pragma unroll 4
        for (int c = 0; c < CC; ++c) {
            u64 xp = dup2(xs[c * 256 + tid]);
            const u64* wrow = (const u64*)(ws + c * DD + d0);
            #pragma unroll
            for (int i = 0; i < 16; ++i) acc[i] = ffma2(xp, wrow[i], acc[i]);
        }

        float* yb = g_y + (size_t)n * DD * TV + (size_t)d0 * TV + tv0 + tid;
        #pragma unroll
        for (int i = 0; i < 16; ++i) {
            float lo, hi; unpack2(acc[i], lo, hi);
            yb[(size_t)(2 * i) * TV]     = lo;
            yb[(size_t)(2 * i + 1) * TV] = hi;
        }
    }
}

// ---------------- k1b: per-channel-d stats of y ----------------
// grid (192, 64): blockIdx.x = d, blockIdx.y = n
__global__ void __launch_bounds__(256) dgcn_k1b_stats() {
    const int d = blockIdx.x, n = blockIdx.y, tid = threadIdx.x;
    const float* row = g_y + (size_t)(n * DD + d) * TV;
    float s = 0.f, ss = 0.f;
    #pragma unroll 5
    for (int i = tid; i < TV; i += 256) { float v = row[i]; s += v; ss += v * v; }
    block_reduce2(s, ss);
    if (tid == 0) { atomicAdd(&g_stat0[d], s); atomicAdd(&g_stat0[DD + d], ss); }
}

// ---------------- k2: fold BN0 into normalized adjacency ----------------
// grid 192 blocks (one per d = k*64+c), 32 threads (lane = column w)
__global__ void dgcn_k2_fold(const float* __restrict__ dA,
                             const float* __restrict__ g0, const float* __restrict__ b0)
{
    const int d = blockIdx.x;
    const int k = d >> 6, c = d & 63, grp = c & 7;
    const int w = threadIdx.x;
    const float* A = dA + (size_t)(k * 8 + grp) * VV * VV;

    float deg = 0.f;
    if (w < VV) {
        #pragma unroll
        for (int v = 0; v < VV; ++v) deg += A[v * VV + w];
    }
    const float mean = g_stat0[d] * (1.0f / NSF);
    const float var  = g_stat0[DD + d] * (1.0f / NSF) - mean * mean;
    const float a = g0[d] * rsqrtf(var + 1e-5f);
    const float b = b0[d] - a * mean;
    const float inv = a / (deg + 1e-3f);

    float* A2 = g_A2 + (size_t)d * VV * 26;
    for (int v = 0; v < VV; ++v) {
        if (w < 26) A2[v * 26 + w] = (w < VV) ? A[v * VV + w] * inv : 0.f;
    }
    if (w < VV) atomicAdd(&g_cvec[c * VV + w], b * deg / (deg + 1e-3f));
}

// ---------------- k3: graph propagation + z stats ----------------
// z[n,c,t,w] = sum_{k,v} y[n,k*64+c,t,v] * A2[k,c,v,w] + cvec[c,w]
// grid (64, 32): blockIdx.x = c; blockIdx.y*256+tid -> (n, t-pair). Pack t/t+1 in f32x2 lanes.
__global__ void __launch_bounds__(256) dgcn_k3_prop() {
    __shared__ u64 a2s[KK * VV * 26];   // value duplicated into both lanes
    __shared__ float cvs[VV];
    const int tid = threadIdx.x;
    const int c = blockIdx.x;

    for (int i = tid; i < KK * VV * 26; i += 256) {
        int k = i / (VV * 26);
        int rem = i - k * (VV * 26);
        float v = g_A2[(size_t)((k << 6) + c) * VV * 26 + rem];
        a2s[i] = pack2(v, v);
    }
    if (tid < VV) cvs[tid] = g_cvec[c * VV + tid];
    __syncthreads();

    const int p = blockIdx.y * 256 + tid;   // 0..8191
    const int n = p >> 7;
    const int t = (p & 127) << 1;

    u64 acc[VV];
    #pragma unroll
    for (int w = 0; w < VV; ++w) acc[w] = 0ull;

    #pragma unroll
    for (int k = 0; k < KK; ++k) {
        const float* yb = g_y + ((size_t)(n * DD + (k << 6) + c) * TT + t) * VV;
        const u64* arow = a2s + k * VV * 26;
        #pragma unroll 1
        for (int v = 0; v < VV; ++v) {
            u64 yp = pack2(yb[v], yb[VV + v]);
            const u64* ar = arow + v * 26;
            #pragma unroll
            for (int w = 0; w < VV; ++w) acc[w] = ffma2(yp, ar[w], acc[w]);
        }
    }

    float s = 0.f, ss = 0.f;
    float* zb = g_z + ((size_t)(n * CC + c) * TT + t) * VV;
    #pragma unroll
    for (int w = 0; w < VV; ++w) {
        float lo, hi; unpack2(acc[w], lo, hi);
        float cv = cvs[w];
        lo += cv; hi += cv;
        zb[w] = lo; zb[VV + w] = hi;
        s += lo + hi; ss += lo * lo + hi * hi;
    }
    block_reduce2(s, ss);
    if (tid == 0) { atomicAdd(&g_stat1[c], s); atomicAdd(&g_stat1[CC + c], ss); }
}

// ---------------- k4: final BN fold ----------------
__global__ void dgcn_k4_bn(const float* __restrict__ g1, const float* __restrict__ b1) {
    int c = threadIdx.x;
    if (c < CC) {
        float mean = g_stat1[c] * (1.0f / NSF);
        float var  = g_stat1[CC + c] * (1.0f / NSF) - mean * mean;
        float a = g1[c] * rsqrtf(var + 1e-5f);
        g_ab1[c] = a;
        g_ab1[CC + c] = b1[c] - a * mean;
    }
}

// ---------------- k5: out = relu(a_c * z + b_c + x0) ----------------
__global__ void __launch_bounds__(256) dgcn_k5_out(const float* __restrict__ x0, float* __restrict__ out) {
    int i = blockIdx.x * 256 + threadIdx.x;       // float4 index, exact coverage
    int c = (i / 1600) & 63;                      // 1600 float4 per (n,c)
    float a = g_ab1[c], b = g_ab1[CC + c];
    float4 zv = ((const float4*)g_z)[i];
    float4 xv = ((const float4*)x0)[i];
    float4 o;
    o.x = fmaxf(fmaf(a, zv.x, b) + xv.x, 0.f);
    o.y = fmaxf(fmaf(a, zv.y, b) + xv.y, 0.f);
    o.z = fmaxf(fmaf(a, zv.z, b) + xv.z, 0.f);
    o.w = fmaxf(fmaf(a, zv.w, b) + xv.w, 0.f);
    ((float4*)out)[i] = o;
}

// ---------------- launch ----------------
extern "C" void kernel_launch(void* const* d_in, const int* in_sizes, int n_in,
                              void* d_out, int out_size)
{
    const float* x0   = (const float*)d_in[0];
    const float* dA   = (const float*)d_in[1];
    const float* W    = (const float*)d_in[2];
    const float* bias = (const float*)d_in[3];
    const float* g0   = (const float*)d_in[4];
    const float* b0   = (const float*)d_in[5];
    const float* g1   = (const float*)d_in[6];
    const float* b1   = (const float*)d_in[7];
    float* out = (float*)d_out;

    const int smem1 = (CC * DD + CC * 256) * (int)sizeof(float);  // 114688
    cudaFuncSetAttribute(dgcn_k1_gemm, cudaFuncAttributeMaxDynamicSharedMemorySize, smem1);

    dgcn_k0_init<<<1, 512>>>();
    dgcn_k1_gemm<<<dim3(25, NB), 256, smem1>>>(x0, W, bias);
    dgcn_k1b_stats<<<dim3(DD, NB), 256>>>();
    dgcn_k2_fold<<<DD, 32>>>(dA, g0, b0);
    dgcn_k3_prop<<<dim3(CC, 32), 256>>>();
    dgcn_k4_bn<<<1, 64>>>(g1, b1);
    dgcn_k5_out<<<(NB * CC * TV) / (4 * 256), 256>>>(x0, out);
}

// round 3
// speedup vs baseline: 1.0501x; 1.0501x over previous
#include <cuda_runtime.h>
#include <cuda_fp16.h>

#define NB 64
#define CC 64
#define TT 256
#define VV 25
#define KK 3
#define DD 192
#define TV 6400
#define NSF 409600.0f

typedef unsigned long long u64;
typedef unsigned int u32;

// ---------------- scratch (static device globals) ----------------
__device__ __half g_yh[(size_t)NB * DD * TV];   // 157MB fp16 intermediate y, [n][d][tv]
__device__ float  g_z[(size_t)NB * CC * TV];    // 105MB intermediate z
__device__ float  g_stat0[2 * DD];
__device__ float  g_stat1[2 * CC];
__device__ float  g_A2[DD * VV * 26];           // BN0-folded normalized adjacency
__device__ float  g_cvec[CC * VV];
__device__ float  g_ab1[2 * CC];

// ---------------- packed f32x2 helpers ----------------
__device__ __forceinline__ u64 pack2(float x, float y) {
    u64 r; asm("mov.b64 %0, {%1, %2};" : "=l"(r) : "f"(x), "f"(y)); return r;
}
__device__ __forceinline__ u64 dup2(float x) {
    u64 r; asm("mov.b64 %0, {%1, %1};" : "=l"(r) : "f"(x)); return r;
}
__device__ __forceinline__ void unpack2(u64 v, float& x, float& y) {
    asm("mov.b64 {%0, %1}, %2;" : "=f"(x), "=f"(y) : "l"(v));
}
__device__ __forceinline__ u64 ffma2(u64 a, u64 b, u64 c) {
    u64 d; asm("fma.rn.f32x2 %0, %1, %2, %3;" : "=l"(d) : "l"(a), "l"(b), "l"(c)); return d;
}

// ---------------- block reduction (256 threads, 2 values) ----------------
__device__ __forceinline__ void block_reduce2(float& s, float& ss) {
    __shared__ float red[16];
    #pragma unroll
    for (int off = 16; off; off >>= 1) {
        s  += __shfl_xor_sync(0xffffffffu, s,  off);
        ss += __shfl_xor_sync(0xffffffffu, ss, off);
    }
    int wid = threadIdx.x >> 5;
    if ((threadIdx.x & 31) == 0) { red[wid] = s; red[8 + wid] = ss; }
    __syncthreads();
    if (threadIdx.x < 8) {
        s = red[threadIdx.x]; ss = red[8 + threadIdx.x];
        #pragma unroll
        for (int off = 4; off; off >>= 1) {
            s  += __shfl_xor_sync(0xffu, s,  off);
            ss += __shfl_xor_sync(0xffu, ss, off);
        }
    }
}

// ---------------- k0: zero accumulators ----------------
__global__ void dgcn_k0() {
    int tid = threadIdx.x;
    for (int i = tid; i < 2 * DD; i += 512) g_stat0[i] = 0.f;
    for (int i = tid; i < 2 * CC; i += 512) g_stat1[i] = 0.f;
    for (int i = tid; i < CC * VV; i += 512) g_cvec[i] = 0.f;
}

// ---------------- k1: GEMM y = W^T x + bias, fp16 output ----------------
// grid (25, 64): tv tile of 256, n. 256 threads = 8 warps.
// Warp w owns d in chunks {dc*64 + w*8 .. +8}; lane owns tv-pairs {lane+32j}, j<4.
// acc packs (tv, tv+1); W duplicated into both lanes in smem (u64 broadcast loads).
__global__ void __launch_bounds__(256) dgcn_k1(const float* __restrict__ x0,
                                               const float* __restrict__ W,
                                               const float* __restrict__ bias)
{
    extern __shared__ char smraw[];
    u64*   wd = (u64*)smraw;                       // [64][192] dup pairs, 96KB
    float* xs = (float*)(smraw + CC * DD * 8);     // [64][256], 64KB
    const int tid = threadIdx.x;
    const int lane = tid & 31, wid = tid >> 5;
    const int n = blockIdx.y;
    const int tv0 = blockIdx.x * 256;

    {   // fill x tile (coalesced float4)
        float4* xs4 = (float4*)xs;
        #pragma unroll 4
        for (int i = tid; i < CC * 256 / 4; i += 256) {
            int c = i >> 6, j = i & 63;
            xs4[i] = *(const float4*)(x0 + (size_t)(n * CC + c) * TV + tv0 + 4 * j);
        }
        // fill duplicated W
        #pragma unroll 4
        for (int i = tid; i < CC * DD; i += 256) wd[i] = dup2(W[i]);
    }
    __syncthreads();

    const u64* xsu = (const u64*)xs;   // [c][128] tv-pairs

    #pragma unroll 1
    for (int dc = 0; dc < 3; ++dc) {
        const int dbase = dc * 64 + wid * 8;
        u64 acc[8][4];
        #pragma unroll
        for (int dd = 0; dd < 8; ++dd) {
            u64 bb = dup2(__ldg(bias + dbase + dd));
            #pragma unroll
            for (int j = 0; j < 4; ++j) acc[dd][j] = bb;
        }

        #pragma unroll 2
        for (int c = 0; c < CC; ++c) {
            u64 xv[4];
            #pragma unroll
            for (int j = 0; j < 4; ++j) xv[j] = xsu[c * 128 + lane + 32 * j];
            const u64* wr = wd + c * DD + dbase;
            #pragma unroll
            for (int dd = 0; dd < 8; ++dd) {
                u64 wv = wr[dd];
                #pragma unroll
                for (int j = 0; j < 4; ++j) acc[dd][j] = ffma2(xv[j], wv, acc[dd][j]);
            }
        }

        #pragma unroll
        for (int dd = 0; dd < 8; ++dd) {
            int d = dbase + dd;
            u32* yb = (u32*)(g_yh + (size_t)(n * DD + d) * TV + tv0);
            #pragma unroll
            for (int j = 0; j < 4; ++j) {
                float lo, hi; unpack2(acc[dd][j], lo, hi);
                __half2 h = __floats2half2_rn(lo, hi);
                yb[lane + 32 * j] = *(u32*)&h;
            }
        }
    }
}

// ---------------- k1b: BN0 stats over fp16 y ----------------
// grid (192, 8): d, 8-n slab per block
__global__ void __launch_bounds__(256) dgcn_k1b() {
    const int d = blockIdx.x, n0 = blockIdx.y * 8, tid = threadIdx.x;
    float s = 0.f, ss = 0.f;
    #pragma unroll 1
    for (int nn = 0; nn < 8; ++nn) {
        const uint4* row = (const uint4*)(g_yh + (size_t)((n0 + nn) * DD + d) * TV);
        for (int i = tid; i < TV / 8; i += 256) {
            uint4 q = row[i];
            const u32 w[4] = {q.x, q.y, q.z, q.w};
            #pragma unroll
            for (int j = 0; j < 4; ++j) {
                float2 f = __half22float2(*(const __half2*)&w[j]);
                s += f.x + f.y;
                ss = fmaf(f.x, f.x, ss);
                ss = fmaf(f.y, f.y, ss);
            }
        }
    }
    block_reduce2(s, ss);
    if (tid == 0) { atomicAdd(&g_stat0[d], s); atomicAdd(&g_stat0[DD + d], ss); }
}

// ---------------- k2: fold BN0 into normalized adjacency ----------------
__global__ void dgcn_k2(const float* __restrict__ dA,
                        const float* __restrict__ g0, const float* __restrict__ b0)
{
    const int d = blockIdx.x;
    const int k = d >> 6, c = d & 63, grp = c & 7;
    const int w = threadIdx.x;
    const float* A = dA + (size_t)(k * 8 + grp) * VV * VV;

    float deg = 0.f;
    if (w < VV) {
        #pragma unroll
        for (int v = 0; v < VV; ++v) deg += A[v * VV + w];
    }
    const float mean = g_stat0[d] * (1.0f / NSF);
    const float var  = g_stat0[DD + d] * (1.0f / NSF) - mean * mean;
    const float a = g0[d] * rsqrtf(var + 1e-5f);
    const float b = b0[d] - a * mean;
    const float inv = a / (deg + 1e-3f);

    float* A2 = g_A2 + (size_t)d * VV * 26;
    for (int v = 0; v < VV; ++v)
        if (w < 26) A2[v * 26 + w] = (w < VV) ? A[v * VV + w] * inv : 0.f;
    if (w < VV) atomicAdd(&g_cvec[c * VV + w], b * deg / (deg + 1e-3f));
}

// ---------------- k3: graph propagation (fp16 y in) + z stats ----------------
// grid (64, 32): c; blockIdx.y*256+tid -> (n, t-pair)
__global__ void __launch_bounds__(256) dgcn_k3() {
    __shared__ u64 a2s[KK * VV * 26];
    __shared__ float cvs[VV];
    const int tid = threadIdx.x;
    const int c = blockIdx.x;

    for (int i = tid; i < KK * VV * 26; i += 256) {
        int k = i / (VV * 26);
        int rem = i - k * (VV * 26);
        float v = g_A2[(size_t)((k << 6) + c) * VV * 26 + rem];
        a2s[i] = pack2(v, v);
    }
    if (tid < VV) cvs[tid] = g_cvec[c * VV + tid];
    __syncthreads();

    const int p = blockIdx.y * 256 + tid;
    const int n = p >> 7;
    const int t = (p & 127) << 1;

    u64 acc[VV];
    #pragma unroll
    for (int w = 0; w < VV; ++w) acc[w] = 0ull;

    float f[2 * VV];
    #pragma unroll
    for (int k = 0; k < KK; ++k) {
        const u32* yw = (const u32*)(g_yh + ((size_t)(n * DD + (k << 6) + c) * TT + t) * VV);
        #pragma unroll
        for (int j = 0; j < VV; ++j) {
            u32 wv = yw[j];
            float2 t2 = __half22float2(*(const __half2*)&wv);
            f[2 * j] = t2.x; f[2 * j + 1] = t2.y;
        }
        const u64* arow = a2s + k * VV * 26;
        #pragma unroll 1
        for (int v = 0; v < VV; ++v) {
            u64 yp = pack2(f[v], f[VV + v]);
            const u64* ar = arow + v * 26;
            #pragma unroll
            for (int w = 0; w < VV; ++w) acc[w] = ffma2(yp, ar[w], acc[w]);
        }
    }

    float s = 0.f, ss = 0.f;
    float* zb = g_z + ((size_t)(n * CC + c) * TT + t) * VV;
    #pragma unroll
    for (int w = 0; w < VV; ++w) {
        float lo, hi; unpack2(acc[w], lo, hi);
        float cv = cvs[w];
        lo += cv; hi += cv;
        zb[w] = lo; zb[VV + w] = hi;
        s += lo + hi; ss += lo * lo + hi * hi;
    }
    block_reduce2(s, ss);
    if (tid == 0) { atomicAdd(&g_stat1[c], s); atomicAdd(&g_stat1[CC + c], ss); }
}

// ---------------- k4: final BN fold ----------------
__global__ void dgcn_k4(const float* __restrict__ g1, const float* __restrict__ b1) {
    int c = threadIdx.x;
    if (c < CC) {
        float mean = g_stat1[c] * (1.0f / NSF);
        float var  = g_stat1[CC + c] * (1.0f / NSF) - mean * mean;
        float a = g1[c] * rsqrtf(var + 1e-5f);
        g_ab1[c] = a;
        g_ab1[CC + c] = b1[c] - a * mean;
    }
}

// ---------------- k5: out = relu(a*z + b + x0) ----------------
__global__ void __launch_bounds__(256) dgcn_k5(const float* __restrict__ x0, float* __restrict__ out) {
    int i = blockIdx.x * 256 + threadIdx.x;
    int c = (i / 1600) & 63;
    float a = g_ab1[c], b = g_ab1[CC + c];
    float4 zv = ((const float4*)g_z)[i];
    float4 xv = ((const float4*)x0)[i];
    float4 o;
    o.x = fmaxf(fmaf(a, zv.x, b) + xv.x, 0.f);
    o.y = fmaxf(fmaf(a, zv.y, b) + xv.y, 0.f);
    o.z = fmaxf(fmaf(a, zv.z, b) + xv.z, 0.f);
    o.w = fmaxf(fmaf(a, zv.w, b) + xv.w, 0.f);
    ((float4*)out)[i] = o;
}

// ---------------- launch ----------------
extern "C" void kernel_launch(void* const* d_in, const int* in_sizes, int n_in,
                              void* d_out, int out_size)
{
    const float* x0   = (const float*)d_in[0];
    const float* dA   = (const float*)d_in[1];
    const float* W    = (const float*)d_in[2];
    const float* bias = (const float*)d_in[3];
    const float* g0   = (const float*)d_in[4];
    const float* b0   = (const float*)d_in[5];
    const float* g1   = (const float*)d_in[6];
    const float* b1   = (const float*)d_in[7];
    float* out = (float*)d_out;

    const int smem1 = CC * DD * 8 + CC * 256 * 4;  // 98304 + 65536 = 163840
    cudaFuncSetAttribute(dgcn_k1, cudaFuncAttributeMaxDynamicSharedMemorySize, smem1);

    dgcn_k0<<<1, 512>>>();
    dgcn_k1<<<dim3(25, NB), 256, smem1>>>(x0, W, bias);
    dgcn_k1b<<<dim3(DD, 8), 256>>>();
    dgcn_k2<<<DD, 32>>>(dA, g0, b0);
    dgcn_k3<<<dim3(CC, 32), 256>>>();
    dgcn_k4<<<1, 64>>>(g1, b1);
    dgcn_k5<<<(NB * CC * TV) / (4 * 256), 256>>>(x0, out);
}

// round 5
// speedup vs baseline: 1.0694x; 1.0184x over previous
#include <cuda_runtime.h>
#include <cuda_fp16.h>

#define NB 64
#define CC 64
#define TT 256
#define VV 25
#define KK 3
#define DD 192
#define TV 6400
#define NSF 409600.0f

typedef unsigned long long u64;
typedef unsigned int u32;

// ---------------- scratch ----------------
__device__ __align__(16) __half g_yh[(size_t)NB * DD * TV];   // 157MB fp16 y [n][d][t][v]
__device__ __align__(16) __half g_zh[(size_t)NB * CC * TV];   // 52MB fp16 z
__device__ float  g_stat0[2 * DD];
__device__ float  g_stat1[2 * CC];
__device__ float  g_A2[DD * VV * 26];
__device__ float  g_cvec[CC * VV];
__device__ float  g_ab1[2 * CC];

// ---------------- packed f32x2 helpers ----------------
__device__ __forceinline__ u64 pack2(float x, float y) {
    u64 r; asm("mov.b64 %0, {%1, %2};" : "=l"(r) : "f"(x), "f"(y)); return r;
}
__device__ __forceinline__ u64 dup2(float x) {
    u64 r; asm("mov.b64 %0, {%1, %1};" : "=l"(r) : "f"(x)); return r;
}
__device__ __forceinline__ void unpack2(u64 v, float& x, float& y) {
    asm("mov.b64 {%0, %1}, %2;" : "=f"(x), "=f"(y) : "l"(v));
}
__device__ __forceinline__ u64 ffma2(u64 a, u64 b, u64 c) {
    u64 d; asm("fma.rn.f32x2 %0, %1, %2, %3;" : "=l"(d) : "l"(a), "l"(b), "l"(c)); return d;
}

// ---------------- k0 ----------------
__global__ void dgcn_k0() {
    int tid = threadIdx.x;
    for (int i = tid; i < 2 * DD; i += 512) g_stat0[i] = 0.f;
    for (int i = tid; i < 2 * CC; i += 512) g_stat1[i] = 0.f;
    for (int i = tid; i < CC * VV; i += 512) g_cvec[i] = 0.f;
}

// ---------------- k1: GEMM + fused BN0 stats ----------------
// grid (25, 64). 256 thr. Warp owns 8 d per dc chunk; lane owns 4 tv-pairs.
__global__ void __launch_bounds__(256) dgcn_k1(const float* __restrict__ x0,
                                               const float* __restrict__ W,
                                               const float* __restrict__ bias)
{
    extern __shared__ char smraw[];
    u64*   wd = (u64*)smraw;                       // [64][192] dup W pairs 96KB
    float* xs = (float*)(smraw + CC * DD * 8);     // [64][256] 64KB
    const int tid = threadIdx.x;
    const int lane = tid & 31, wid = tid >> 5;
    const int n = blockIdx.y;
    const int tv0 = blockIdx.x * 256;

    {
        float4* xs4 = (float4*)xs;
        #pragma unroll 4
        for (int i = tid; i < CC * 256 / 4; i += 256) {
            int c = i >> 6, j = i & 63;
            xs4[i] = *(const float4*)(x0 + (size_t)(n * CC + c) * TV + tv0 + 4 * j);
        }
        #pragma unroll 4
        for (int i = tid; i < CC * DD; i += 256) wd[i] = dup2(W[i]);
    }
    __syncthreads();

    const u64* xsu = (const u64*)xs;

    #pragma unroll 1
    for (int dc = 0; dc < 3; ++dc) {
        const int dbase = dc * 64 + wid * 8;
        u64 acc[8][4];
        #pragma unroll
        for (int dd = 0; dd < 8; ++dd) {
            u64 bb = dup2(__ldg(bias + dbase + dd));
            #pragma unroll
            for (int j = 0; j < 4; ++j) acc[dd][j] = bb;
        }

        #pragma unroll 2
        for (int c = 0; c < CC; ++c) {
            u64 xv[4];
            #pragma unroll
            for (int j = 0; j < 4; ++j) xv[j] = xsu[c * 128 + lane + 32 * j];
            const u64* wr = wd + c * DD + dbase;
            #pragma unroll
            for (int dd = 0; dd < 8; ++dd) {
                u64 wv = wr[dd];
                #pragma unroll
                for (int j = 0; j < 4; ++j) acc[dd][j] = ffma2(xv[j], wv, acc[dd][j]);
            }
        }

        #pragma unroll
        for (int dd = 0; dd < 8; ++dd) {
            const int d = dbase + dd;
            u32* yb = (u32*)(g_yh + (size_t)(n * DD + d) * TV + tv0);
            float s = 0.f, ss = 0.f;
            #pragma unroll
            for (int j = 0; j < 4; ++j) {
                float lo, hi; unpack2(acc[dd][j], lo, hi);
                s += lo + hi;
                ss = fmaf(lo, lo, ss); ss = fmaf(hi, hi, ss);
                __half2 h = __floats2half2_rn(lo, hi);
                yb[lane + 32 * j] = *(u32*)&h;
            }
            #pragma unroll
            for (int off = 16; off; off >>= 1) {
                s  += __shfl_xor_sync(0xffffffffu, s,  off);
                ss += __shfl_xor_sync(0xffffffffu, ss, off);
            }
            if (lane == 0) {
                atomicAdd(&g_stat0[d], s);
                atomicAdd(&g_stat0[DD + d], ss);
            }
        }
    }
}

// ---------------- k2: fold BN0 into normalized adjacency ----------------
__global__ void dgcn_k2(const float* __restrict__ dA,
                        const float* __restrict__ g0, const float* __restrict__ b0)
{
    const int d = blockIdx.x;
    const int k = d >> 6, c = d & 63, grp = c & 7;
    const int w = threadIdx.x;
    const float* A = dA + (size_t)(k * 8 + grp) * VV * VV;

    float deg = 0.f;
    if (w < VV) {
        #pragma unroll
        for (int v = 0; v < VV; ++v) deg += A[v * VV + w];
    }
    const float mean = g_stat0[d] * (1.0f / NSF);
    const float var  = g_stat0[DD + d] * (1.0f / NSF) - mean * mean;
    const float a = g0[d] * rsqrtf(var + 1e-5f);
    const float b = b0[d] - a * mean;
    const float inv = a / (deg + 1e-3f);

    float* A2 = g_A2 + (size_t)d * VV * 26;
    for (int v = 0; v < VV; ++v)
        if (w < 26) A2[v * 26 + w] = (w < VV) ? A[v * VV + w] * inv : 0.f;
    if (w < VV) atomicAdd(&g_cvec[c * VV + w], b * deg / (deg + 1e-3f));
}

// ---------------- k3: staged propagation ----------------
// grid (64, 32): c, n-pair. 128 threads = one t-pair each. Dynamic smem, explicit layout:
//   [0, 76800)          sy: 6 y rows [nn*3+k][3200 u32] (16-aligned base)
//   [76800, 92400)      a2s: 1950 u64 dup adjacency
//   [92400, 92500)      cvs: 25 floats
//   [92512, 92544)      red: 8 floats
#define SY_BYTES  76800
#define K3_SMEM   92544
__global__ void __launch_bounds__(128) dgcn_k3() {
    extern __shared__ char sm3[];
    u32*   sy  = (u32*)sm3;
    u64*   a2s = (u64*)(sm3 + SY_BYTES);
    float* cvs = (float*)(sm3 + SY_BYTES + 15600);
    float* red = (float*)(sm3 + SY_BYTES + 15712);

    const int tid = threadIdx.x;
    const int c = blockIdx.x;
    const int n0 = blockIdx.y * 2;

    for (int i = tid; i < KK * VV * 26; i += 128) {
        int k = i / (VV * 26);
        int rem = i - k * (VV * 26);
        float v = g_A2[(size_t)((k << 6) + c) * VV * 26 + rem];
        a2s[i] = pack2(v, v);
    }
    if (tid < VV) cvs[tid] = g_cvec[c * VV + tid];

    // stage 6 y rows (2 n x 3 k): 6 x 800 uint4, coalesced
    for (int i = tid; i < 6 * 800; i += 128) {
        int r = i / 800, j = i - r * 800;
        int nn = r / 3, k = r - nn * 3;
        const uint4* src = (const uint4*)(g_yh + (size_t)((n0 + nn) * DD + (k << 6) + c) * TV);
        ((uint4*)sy)[i] = src[j];   // row r at uint4 offset r*800
    }
    __syncthreads();

    const int tp = tid;            // t-pair 0..127
    float s = 0.f, ss = 0.f;

    #pragma unroll 1
    for (int nn = 0; nn < 2; ++nn) {
        u64 acc[VV];
        #pragma unroll
        for (int w = 0; w < VV; ++w) acc[w] = 0ull;

        #pragma unroll
        for (int k = 0; k < KK; ++k) {
            const u32* pa = sy + (nn * KK + k) * 3200 + 25 * tp;  // 50 halves for t=2tp,2tp+1
            float f[50];
            #pragma unroll
            for (int j = 0; j < 25; ++j) {
                u32 wv = pa[j];
                float2 t2 = __half22float2(*(const __half2*)&wv);
                f[2 * j] = t2.x; f[2 * j + 1] = t2.y;
            }
            const u64* ar = a2s + k * VV * 26;
            #pragma unroll 1
            for (int v = 0; v < VV; ++v) {
                u64 yp = pack2(f[v], f[VV + v]);
                const u64* arv = ar + v * 26;
                #pragma unroll
                for (int w = 0; w < VV; ++w) acc[w] = ffma2(yp, arv[w], acc[w]);
            }
        }

        __syncthreads();  // all reads of sy rows for this nn done before overwrite below
        // z for batch nn goes into bytes [nn*12800, nn*12800+12800) — row nn's region,
        // which is only read during iteration nn (nn=1 reads rows 3..5 at >=38400).
        __half* zs = (__half*)(sm3 + nn * 12800);
        #pragma unroll
        for (int w = 0; w < VV; ++w) {
            float lo, hi; unpack2(acc[w], lo, hi);
            float cv = cvs[w];
            lo += cv; hi += cv;
            s += lo + hi; ss = fmaf(lo, lo, ss); ss = fmaf(hi, hi, ss);
            zs[50 * tp + w] = __float2half(lo);
            zs[50 * tp + 25 + w] = __float2half(hi);
        }
        __syncthreads();
    }

    // stats reduce + atomics
    #pragma unroll
    for (int off = 16; off; off >>= 1) {
        s  += __shfl_xor_sync(0xffffffffu, s,  off);
        ss += __shfl_xor_sync(0xffffffffu, ss, off);
    }
    if ((tid & 31) == 0) { red[tid >> 5] = s; red[4 + (tid >> 5)] = ss; }
    __syncthreads();
    if (tid == 0) {
        atomicAdd(&g_stat1[c], red[0] + red[1] + red[2] + red[3]);
        atomicAdd(&g_stat1[CC + c], red[4] + red[5] + red[6] + red[7]);
    }

    // coalesced z store: 2 rows x 800 uint4  (z region = bytes [0, 25600) of sm3)
    for (int i = tid; i < 2 * 800; i += 128) {
        int nn = i / 800, j = i - nn * 800;
        uint4* dst = (uint4*)(g_zh + (size_t)((n0 + nn) * CC + c) * TV);
        dst[j] = ((const uint4*)sm3)[i];
    }
}

// ---------------- k4 ----------------
__global__ void dgcn_k4(const float* __restrict__ g1, const float* __restrict__ b1) {
    int c = threadIdx.x;
    if (c < CC) {
        float mean = g_stat1[c] * (1.0f / NSF);
        float var  = g_stat1[CC + c] * (1.0f / NSF) - mean * mean;
        float a = g1[c] * rsqrtf(var + 1e-5f);
        g_ab1[c] = a;
        g_ab1[CC + c] = b1[c] - a * mean;
    }
}

// ---------------- k5: out = relu(a*z + b + x0), 8 elems/thread ----------------
__global__ void __launch_bounds__(256) dgcn_k5(const float* __restrict__ x0, float* __restrict__ out) {
    size_t base = ((size_t)blockIdx.x * 256 + threadIdx.x) * 8;
    int c = (int)((base / TV) & 63);
    float a = g_ab1[c], b = g_ab1[CC + c];
    uint4 zq = *(const uint4*)(g_zh + base);
    float4 x1 = *(const float4*)(x0 + base);
    float4 x2 = *(const float4*)(x0 + base + 4);
    float2 z0 = __half22float2(*(__half2*)&zq.x);
    float2 z1 = __half22float2(*(__half2*)&zq.y);
    float2 z2 = __half22float2(*(__half2*)&zq.z);
    float2 z3 = __half22float2(*(__half2*)&zq.w);
    float4 o1, o2;
    o1.x = fmaxf(fmaf(a, z0.x, b) + x1.x, 0.f);
    o1.y = fmaxf(fmaf(a, z0.y, b) + x1.y, 0.f);
    o1.z = fmaxf(fmaf(a, z1.x, b) + x1.z, 0.f);
    o1.w = fmaxf(fmaf(a, z1.y, b) + x1.w, 0.f);
    o2.x = fmaxf(fmaf(a, z2.x, b) + x2.x, 0.f);
    o2.y = fmaxf(fmaf(a, z2.y, b) + x2.y, 0.f);
    o2.z = fmaxf(fmaf(a, z3.x, b) + x2.z, 0.f);
    o2.w = fmaxf(fmaf(a, z3.y, b) + x2.w, 0.f);
    *(float4*)(out + base) = o1;
    *(float4*)(out + base + 4) = o2;
}

// ---------------- launch ----------------
extern "C" void kernel_launch(void* const* d_in, const int* in_sizes, int n_in,
                              void* d_out, int out_size)
{
    const float* x0   = (const float*)d_in[0];
    const float* dA   = (const float*)d_in[1];
    const float* W    = (const float*)d_in[2];
    const float* bias = (const float*)d_in[3];
    const float* g0   = (const float*)d_in[4];
    const float* b0   = (const float*)d_in[5];
    const float* g1   = (const float*)d_in[6];
    const float* b1   = (const float*)d_in[7];
    float* out = (float*)d_out;

    const int smem1 = CC * DD * 8 + CC * 256 * 4;  // 163840
    cudaFuncSetAttribute(dgcn_k1, cudaFuncAttributeMaxDynamicSharedMemorySize, smem1);
    cudaFuncSetAttribute(dgcn_k3, cudaFuncAttributeMaxDynamicSharedMemorySize, K3_SMEM);

    dgcn_k0<<<1, 512>>>();
    dgcn_k1<<<dim3(25, NB), 256, smem1>>>(x0, W, bias);
    dgcn_k2<<<DD, 32>>>(dA, g0, b0);
    dgcn_k3<<<dim3(CC, NB / 2), 128, K3_SMEM>>>();
    dgcn_k4<<<1, 64>>>(g1, b1);
    dgcn_k5<<<(int)(((size_t)NB * CC * TV) / (8 * 256)), 256>>>(x0, out);
}